// round 16
// baseline (speedup 1.0000x reference)
#include <cuda_runtime.h>
#include <mma.h>
#include <cstdint>

using namespace nvcuda;

// ---------------------------------------------------------------------------
// GNN_83356725281276 : 2-layer dense GCN + segment readout + MLP head
//   x_in [16384,64] f32, adj [16384,16384] f32, idx [16384] (int32 OR int64 —
//   detected at runtime), weights per reference. Output: [128,10] f32.
//
// NO inline asm, NO dynamic shared memory, NO cudaFuncSetAttribute, NO host
// static state (the round-13 removal of those eliminated the device trap).
// This round fixes the idx dtype: JAX default config downgrades the
// reference's astype(int64) to int32, so the index buffer is read via a
// runtime int32/int64 detector instead of assuming long long.
// ---------------------------------------------------------------------------

#define N_NODES 16384
#define DIM     64
#define NG      128
#define NCLS    10

__device__ float g_H [N_NODES * DIM];   // adj @ x_in
__device__ float g_X1[N_NODES * DIM];   // relu((H+x_in) W1^T + b1)
__device__ float g_H2[N_NODES * DIM];   // adj @ X1
__device__ float g_X2[N_NODES * DIM];   // relu((H2+X1) W2^T + b2)
__device__ float g_SEG[NG * DIM];
__device__ int   g_off[NG + 1];

// ---------------------------------------------------------------------------
// Propagation GEMM:  C[m,n] = sum_k adj[m,k] * B[k,n]      (pure adj @ B)
// M = K = 16384, N = 64. tf32 WMMA, register-prefetch single-stage smem.
// grid = 128 CTAs (128 rows each), block = 256 (8 warps, 4m x 2n),
// warp tile 32x32 = 2x2 wmma m16n16k8 tiles.
// ---------------------------------------------------------------------------
#define BM 128
#define BK 32
#define AS 36   // A smem row stride (floats): 36 mod 32 = 4 -> spread banks
#define BS 68   // B smem row stride (floats): 68 mod 32 = 4

__global__ __launch_bounds__(256)
void gemm_prop(const float* __restrict__ A,     // adj [16384,16384]
               const float* __restrict__ B_in,  // x_in (layer 0)
               int layer)                       // 0: x_in->g_H, 1: g_X1->g_H2
{
    __shared__ float As[BM * AS];   // 18,432 B
    __shared__ float Bs[BK * BS];   //  8,704 B   (total 26.5 KB static)

    const float* __restrict__ B = (layer == 0) ? B_in : g_X1;
    float* __restrict__       C = (layer == 0) ? g_H  : g_H2;

    const int tid  = threadIdx.x;
    const int warp = tid >> 5;
    const int wm   = warp & 3;    // 0..3 : 32-row group
    const int wn   = warp >> 2;   // 0..1 : 32-col group
    const int rowBase = blockIdx.x * BM;

    // static copy maps
    // A tile 128x32 = 1024 float4 -> 4 per thread
    const int a_r0 = tid >> 3;          // +32*i
    const int a_c  = (tid & 7) * 4;
    // B tile 32x64 = 512 float4 -> 2 per thread
    const int b_r0 = tid >> 4;          // +16*i
    const int b_c  = (tid & 15) * 4;

    wmma::fragment<wmma::accumulator, 16, 16, 8, float> acc[2][2];
#pragma unroll
    for (int m = 0; m < 2; m++)
#pragma unroll
        for (int n = 0; n < 2; n++)
            wmma::fill_fragment(acc[m][n], 0.0f);

    float4 pa[4], pb[2];

    // prefetch k0 = 0
#pragma unroll
    for (int i = 0; i < 4; i++)
        pa[i] = *reinterpret_cast<const float4*>(
                    &A[(size_t)(rowBase + a_r0 + 32 * i) * N_NODES + a_c]);
#pragma unroll
    for (int i = 0; i < 2; i++)
        pb[i] = *reinterpret_cast<const float4*>(
                    &B[(size_t)(b_r0 + 16 * i) * DIM + b_c]);

    const int nK = N_NODES / BK;  // 512
    for (int kt = 0; kt < nK; kt++) {
        // drain prefetch registers into smem
#pragma unroll
        for (int i = 0; i < 4; i++)
            *reinterpret_cast<float4*>(&As[(a_r0 + 32 * i) * AS + a_c]) = pa[i];
#pragma unroll
        for (int i = 0; i < 2; i++)
            *reinterpret_cast<float4*>(&Bs[(b_r0 + 16 * i) * BS + b_c]) = pb[i];
        __syncthreads();

        // issue next tile's loads (overlap with compute below)
        if (kt + 1 < nK) {
            const int k0 = (kt + 1) * BK;
#pragma unroll
            for (int i = 0; i < 4; i++)
                pa[i] = *reinterpret_cast<const float4*>(
                            &A[(size_t)(rowBase + a_r0 + 32 * i) * N_NODES + k0 + a_c]);
#pragma unroll
            for (int i = 0; i < 2; i++)
                pb[i] = *reinterpret_cast<const float4*>(
                            &B[(size_t)(k0 + b_r0 + 16 * i) * DIM + b_c]);
        }

#pragma unroll
        for (int k8 = 0; k8 < 4; k8++) {
            wmma::fragment<wmma::matrix_a, 16, 16, 8, wmma::precision::tf32,
                           wmma::row_major> af[2];
            wmma::fragment<wmma::matrix_b, 16, 16, 8, wmma::precision::tf32,
                           wmma::row_major> bf[2];
            wmma::load_matrix_sync(af[0], &As[(wm * 32)      * AS + k8 * 8], AS);
            wmma::load_matrix_sync(af[1], &As[(wm * 32 + 16) * AS + k8 * 8], AS);
            wmma::load_matrix_sync(bf[0], &Bs[(k8 * 8) * BS + wn * 32],      BS);
            wmma::load_matrix_sync(bf[1], &Bs[(k8 * 8) * BS + wn * 32 + 16], BS);
#pragma unroll
            for (int m = 0; m < 2; m++)
#pragma unroll
                for (int t = 0; t < af[m].num_elements; t++)
                    af[m].x[t] = wmma::__float_to_tf32(af[m].x[t]);
#pragma unroll
            for (int n = 0; n < 2; n++)
#pragma unroll
                for (int t = 0; t < bf[n].num_elements; t++)
                    bf[n].x[t] = wmma::__float_to_tf32(bf[n].x[t]);
#pragma unroll
            for (int m = 0; m < 2; m++)
#pragma unroll
                for (int n = 0; n < 2; n++)
                    wmma::mma_sync(acc[m][n], af[m], bf[n], acc[m][n]);
        }
        __syncthreads();
    }

    // epilogue: write pure adj@B (self-loop handled in fc_relu)
#pragma unroll
    for (int m = 0; m < 2; m++)
#pragma unroll
        for (int n = 0; n < 2; n++)
            wmma::store_matrix_sync(
                &C[(size_t)(rowBase + wm * 32 + 16 * m) * DIM + wn * 32 + 16 * n],
                acc[m][n], DIM, wmma::mem_row_major);
}

// ---------------------------------------------------------------------------
// FC + ReLU with fused self-loop add:
//   Out[n,o] = relu(b[o] + sum_h (In[n,h] + Bprev[n,h]) * W[o,h])
// layer 0: (g_H + x_in) -> g_X1 ; layer 1: (g_H2 + g_X1) -> g_X2
// ---------------------------------------------------------------------------
__global__ __launch_bounds__(256)
void fc_relu(const float* __restrict__ W, const float* __restrict__ bias,
             const float* __restrict__ x_in, int layer)
{
    const float* __restrict__ In    = (layer == 0) ? g_H  : g_H2;
    const float* __restrict__ Bprev = (layer == 0) ? x_in : g_X1;
    float* __restrict__       Out   = (layer == 0) ? g_X1 : g_X2;

    __shared__ float in_s[32 * 65];
    __shared__ float Ws[64 * 65];
    const int tid = threadIdx.x;
    const int rowBase = blockIdx.x * 32;

#pragma unroll
    for (int i = 0; i < 8; i++) {
        int f = tid + i * 256;        // 0..2047
        int r = f >> 6, h = f & 63;
        size_t g = (size_t)(rowBase + r) * DIM + h;
        in_s[r * 65 + h] = In[g] + Bprev[g];   // self-loop term
    }
#pragma unroll
    for (int i = 0; i < 16; i++) {
        int f = tid + i * 256;        // 0..4095
        int o = f >> 6, h = f & 63;
        Ws[o * 65 + h] = W[f];
    }
    __syncthreads();

    const int r  = tid >> 3;          // 0..31
    const int o0 = tid & 7;
    float a[8];
#pragma unroll
    for (int j = 0; j < 8; j++) a[j] = bias[o0 + 8 * j];

#pragma unroll
    for (int h = 0; h < 64; h++) {
        const float v = in_s[r * 65 + h];
#pragma unroll
        for (int j = 0; j < 8; j++)
            a[j] += v * Ws[(o0 + 8 * j) * 65 + h];
    }
#pragma unroll
    for (int j = 0; j < 8; j++)
        Out[(size_t)(rowBase + r) * DIM + o0 + 8 * j] = fmaxf(a[j], 0.f);
}

// ---------------------------------------------------------------------------
// Segment offsets with runtime int32/int64 detection.
//
// The reference does idx.astype(jnp.int64), but JAX's default dtype
// canonicalization (x64 disabled) makes the materialized buffer int32.
// Detection: view the buffer as int32 and scan the first 16384 words
// (in-bounds under BOTH hypotheses). A genuinely-int32 sorted index is
// non-decreasing; an int64 buffer (values 0..127, little-endian) views as
// v0,0,v1,0,... which must contain a decrease once values exceed 0.
// Then binary-search offsets with stride 2 (int64) or 1 (int32).
// ---------------------------------------------------------------------------
__global__ __launch_bounds__(256)
void offsets_kernel(const int* __restrict__ idx32)
{
    const int t = threadIdx.x;

    int dec = 0;
    for (int i = t; i < N_NODES - 1; i += 256)
        if (idx32[i + 1] < idx32[i]) dec = 1;
    const int is64 = __syncthreads_or(dec);

    if (t > NG) return;
    int lo = 0, hi = N_NODES;         // first position with value(pos) >= t
    while (lo < hi) {
        int mid = (lo + hi) >> 1;
        int v = is64 ? idx32[2 * mid] : idx32[mid];
        if (v < t) lo = mid + 1; else hi = mid;
    }
    g_off[t] = lo;
}

__global__ __launch_bounds__(256)
void segsum_kernel()
{
    __shared__ float red[4][64];
    const int g   = blockIdx.x;
    const int h   = threadIdx.x & 63;
    const int grp = threadIdx.x >> 6;   // 0..3
    const int s = g_off[g], e = g_off[g + 1];
    float acc = 0.f;
    for (int n = s + grp; n < e; n += 4)
        acc += g_X2[(size_t)n * DIM + h];
    red[grp][h] = acc;
    __syncthreads();
    if (grp == 0)
        g_SEG[g * DIM + h] = red[0][h] + red[1][h] + red[2][h] + red[3][h];
}

// ---------------------------------------------------------------------------
// Head: relu(SEG@W3^T+b3) @ W4^T + b4 -> log_softmax.  grid=128, block=64.
// ---------------------------------------------------------------------------
__global__ __launch_bounds__(64)
void head_kernel(const float* __restrict__ W3, const float* __restrict__ b3,
                 const float* __restrict__ W4, const float* __restrict__ b4,
                 float* __restrict__ out)
{
    __shared__ float w3s[64 * 64];
    __shared__ float xr[64], x3[64], lg[NCLS];
    const int g = blockIdx.x, t = threadIdx.x;

    for (int i = t; i < 64 * 64; i += 64) w3s[i] = W3[i];
    xr[t] = g_SEG[g * DIM + t];
    __syncthreads();

    float a = b3[t];
#pragma unroll
    for (int h = 0; h < 64; h++) a += xr[h] * w3s[t * 64 + h];
    x3[t] = fmaxf(a, 0.f);
    __syncthreads();

    if (t < NCLS) {
        float z = b4[t];
#pragma unroll
        for (int h = 0; h < 64; h++) z += x3[h] * W4[t * 64 + h];
        lg[t] = z;
    }
    __syncthreads();

    if (t == 0) {
        float m = lg[0];
        for (int c = 1; c < NCLS; c++) m = fmaxf(m, lg[c]);
        float s = 0.f;
        for (int c = 0; c < NCLS; c++) s += expf(lg[c] - m);
        const float l = logf(s);
        for (int c = 0; c < NCLS; c++) out[g * NCLS + c] = lg[c] - m - l;
    }
}

// ---------------------------------------------------------------------------
// launch: kernel launches only — no attributes, no symbol queries, no state
// ---------------------------------------------------------------------------
extern "C" void kernel_launch(void* const* d_in, const int* in_sizes, int n_in,
                              void* d_out, int out_size)
{
    const float* x_in = (const float*)d_in[0];
    const float* adj  = (const float*)d_in[1];
    const int*   idx  = (const int*)d_in[2];     // int32 OR int64: detected on device
    const float* W1 = (const float*)d_in[3];
    const float* b1 = (const float*)d_in[4];
    const float* W2 = (const float*)d_in[5];
    const float* b2 = (const float*)d_in[6];
    const float* W3 = (const float*)d_in[7];
    const float* b3 = (const float*)d_in[8];
    const float* W4 = (const float*)d_in[9];
    const float* b4 = (const float*)d_in[10];
    float* out = (float*)d_out;

    // layer 1
    gemm_prop<<<N_NODES / BM, 256>>>(adj, x_in, 0);
    fc_relu<<<N_NODES / 32, 256>>>(W1, b1, x_in, 0);

    // layer 2
    gemm_prop<<<N_NODES / BM, 256>>>(adj, x_in, 1);
    fc_relu<<<N_NODES / 32, 256>>>(W2, b2, x_in, 1);

    // readout
    offsets_kernel<<<1, 256>>>(idx);
    segsum_kernel<<<NG, 256>>>();

    // head + log_softmax
    head_kernel<<<NG, 64>>>(W3, b3, W4, b4, out);
}